// round 3
// baseline (speedup 1.0000x reference)
#include <cuda_runtime.h>
#include <math.h>

#define NB 32
#define NS 2048
#define NH 768
#define NO 768
#define NK 64
#define GRID 148
#define TPB 256
#define HSPLIT 48
#define HCHUNK (NH / HSPLIT)   // 16

// inter-phase scratch (no cudaMalloc allowed)
__device__ float g_score[NB * 72];                    // [b][0..63] token scores, [64] subject+ba
__device__ float g_pooled[NB * NH];
__device__ float g_part[HSPLIT * NB * NO];            // 4.7 MB partials
__device__ unsigned long long g_bar[4];               // monotonic barrier counters
__device__ float g_sink;                              // prefetch DCE sink

// grid-wide barrier: monotonic epoch counter, reset-free across graph replays
__device__ __forceinline__ void grid_barrier(int i)
{
    __syncthreads();
    if (threadIdx.x == 0) {
        __threadfence();
        unsigned long long ticket = atomicAdd(&g_bar[i], 1ULL);
        unsigned long long target = (ticket / GRID + 1ULL) * GRID;
        volatile unsigned long long* p = &g_bar[i];
        while (*p < target) __nanosleep(64);
        __threadfence();
    }
    __syncthreads();
}

__global__ void __launch_bounds__(TPB)
fused_kernel(const float* __restrict__ hidden,        // (B,S,H)
             const int*   __restrict__ token_idxs,    // (B,K) sorted
             const float* __restrict__ subject_hidden,// (B,H)
             const float* __restrict__ Wa,            // (2H,1)
             const float* __restrict__ ba,            // (1,)
             const float* __restrict__ Wo,            // (H,O)
             const float* __restrict__ bo,            // (O,)
             float*       __restrict__ out_t,         // (B,O)
             float*       __restrict__ out_aw)        // (B,S)
{
    const int tid  = threadIdx.x;
    const int warp = tid >> 5;
    const int lane = tid & 31;
    const int blk  = blockIdx.x;

    __shared__ int   s_idx[NK];
    __shared__ float s_sc[NK];
    __shared__ float s_w[NK];
    __shared__ float s_p[NB * HCHUNK];   // phase D staging (2 KB)

    // ============ PHASE A: zero aw + all 2080 score dots ============
    {
        // zero attention weights: 16384 float4 over 37888 threads
        int gid = blk * TPB + tid;
        if (gid < (NB * NS) / 4)
            ((float4*)out_aw)[gid] = make_float4(0.f, 0.f, 0.f, 0.f);

        // score dots: warp-level tasks, 2080 total over 1184 warps
        int wgid = blk * 8 + warp;
        for (int t = wgid; t < NB * NK + NB; t += GRID * 8) {
            const float4* row;
            const float4* wv;
            int b, j;
            if (t < NB * NK) {
                b = t >> 6; j = t & 63;
                int ix = token_idxs[b * NK + j];
                row = (const float4*)(hidden + ((size_t)b * NS + ix) * NH);
                wv  = (const float4*)(Wa + NH);
            } else {
                b = t - NB * NK; j = 64;
                row = (const float4*)(subject_hidden + (size_t)b * NH);
                wv  = (const float4*)Wa;
            }
            float p = 0.f;
            #pragma unroll
            for (int i = 0; i < 6; i++) {          // 6*32 float4 = 768
                float4 r = row[i * 32 + lane];
                float4 w = wv[i * 32 + lane];
                p = fmaf(r.x, w.x, p); p = fmaf(r.y, w.y, p);
                p = fmaf(r.z, w.z, p); p = fmaf(r.w, w.w, p);
            }
            #pragma unroll
            for (int o = 16; o; o >>= 1) p += __shfl_xor_sync(0xffffffffu, p, o);
            if (lane == 0)
                g_score[b * 72 + j] = (j == 64) ? (p + ba[0]) : p;
        }
    }
    grid_barrier(0);

    // ============ PHASE C: softmax (local) + pool + aw scatter; Wo prefetch ============
    if (blk < NB * 3) {                      // 96 pool tasks: (b, 256-col tile)
        const int b    = blk / 3;
        const int tile = blk % 3;

        if (tid < NK) {
            s_idx[tid] = token_idxs[b * NK + tid];
            s_sc[tid]  = g_score[b * 72 + tid];
        }
        __syncthreads();
        const float subj = g_score[b * 72 + 64];

        if (tid < 32) {                      // dedup'd softmax, 2 entries/lane
            float sc[2]; bool v[2];
            float m = -1e30f;
            #pragma unroll
            for (int r = 0; r < 2; r++) {
                int j = lane + 32 * r;
                v[r]  = (j == 0) || (s_idx[j] != s_idx[j - 1]);
                sc[r] = s_sc[j] + subj;
                m = fmaxf(m, v[r] ? sc[r] : -1e30f);
            }
            #pragma unroll
            for (int o = 16; o; o >>= 1) m = fmaxf(m, __shfl_xor_sync(0xffffffffu, m, o));
            float e[2], sum = 0.f;
            #pragma unroll
            for (int r = 0; r < 2; r++) { e[r] = v[r] ? expf(sc[r] - m) : 0.f; sum += e[r]; }
            #pragma unroll
            for (int o = 16; o; o >>= 1) sum += __shfl_xor_sync(0xffffffffu, sum, o);
            float inv = 1.0f / sum;
            #pragma unroll
            for (int r = 0; r < 2; r++) s_w[lane + 32 * r] = e[r] * inv;
        }
        __syncthreads();

        if (tile == 0 && tid < NK) {         // scatter aw (zeroed in phase A)
            bool valid = (tid == 0) || (s_idx[tid] != s_idx[tid - 1]);
            if (valid) out_aw[(size_t)b * NS + s_idx[tid]] = s_w[tid];
        }

        // pool 256 columns over 64 (L2-hot) rows
        const float* hb = hidden + (size_t)b * NS * NH;
        const int h = tile * 256 + tid;
        float acc = 0.f;
        #pragma unroll 8
        for (int j = 0; j < NK; j++)
            acc = fmaf(s_w[j], hb[(size_t)s_idx[j] * NH + h], acc);
        g_pooled[b * NH + h] = acc;
    } else {
        // 52 blocks prefetch Wo into L2 for phase D
        const float4* w4 = (const float4*)Wo;
        float acc = 0.f;
        int nth = (GRID - NB * 3) * TPB;
        int g0  = (blk - NB * 3) * TPB + tid;
        for (int i = g0; i < (NH * NO) / 4; i += nth) {
            float4 w = w4[i];
            acc += w.x + w.y + w.z + w.w;
        }
        if (acc == 123456789.0f) g_sink = acc;   // never true; defeats DCE
    }
    grid_barrier(1);

    // ============ PHASE D: GEMM partials (Wo read once, from L2) ============
    if (blk < 3 * HSPLIT) {                  // 144 tasks: (o-tile of 256) x (h-split)
        const int otile = blk % 3;
        const int hs    = blk / 3;
        const int h0    = hs * HCHUNK;

        #pragma unroll
        for (int i = tid; i < NB * HCHUNK; i += TPB) {
            int bb = i / HCHUNK, hh = i % HCHUNK;
            s_p[i] = g_pooled[bb * NH + h0 + hh];
        }
        __syncthreads();

        const int o = otile * 256 + tid;
        float acc[NB];
        #pragma unroll
        for (int bb = 0; bb < NB; bb++) acc[bb] = 0.f;

        const float* w = Wo + (size_t)h0 * NO + o;
        #pragma unroll
        for (int hh = 0; hh < HCHUNK; hh++) {
            float wv = w[(size_t)hh * NO];
            #pragma unroll
            for (int bb = 0; bb < NB; bb++)
                acc[bb] = fmaf(s_p[bb * HCHUNK + hh], wv, acc[bb]);
        }
        float* dst = g_part + ((size_t)hs * NB) * NO + o;
        #pragma unroll
        for (int bb = 0; bb < NB; bb++)
            dst[(size_t)bb * NO] = acc[bb];
    }
    grid_barrier(2);

    // ============ PHASE E: reduce partials + bias + tanh ============
    {
        int gid = blk * TPB + tid;
        if (gid < NB * NO) {
            float sum = bo[gid % NO];
            #pragma unroll
            for (int hs = 0; hs < HSPLIT; hs++)
                sum += g_part[(size_t)hs * NB * NO + gid];
            out_t[gid] = tanhf(sum);
        }
    }
}

// ---------------------------------------------------------------------------
extern "C" void kernel_launch(void* const* d_in, const int* in_sizes, int n_in,
                              void* d_out, int out_size)
{
    const float* hidden         = (const float*)d_in[0];
    const int*   token_idxs     = (const int*)  d_in[1];
    const float* subject_hidden = (const float*)d_in[2];
    const float* Wa             = (const float*)d_in[3];
    const float* ba             = (const float*)d_in[4];
    const float* Wo             = (const float*)d_in[5];
    const float* bo             = (const float*)d_in[6];

    float* out_transformed = (float*)d_out;              // (B,O)
    float* out_aw          = (float*)d_out + NB * NO;    // (B,S)

    fused_kernel<<<GRID, TPB>>>(hidden, token_idxs, subject_hidden,
                                Wa, ba, Wo, bo, out_transformed, out_aw);
}

// round 4
// speedup vs baseline: 1.0550x; 1.0550x over previous
#include <cuda_runtime.h>
#include <math.h>

#define NB 32
#define NS 2048
#define NH 768
#define NO 768
#define NK 64
#define GRID 148
#define TPB 512
#define NWARP (TPB / 32)            // 16
#define HSPLIT 48
#define HCHUNK (NH / HSPLIT)        // 16
#define NTASKS (NB * NK + NB)       // 2080 score dots

// inter-phase scratch (no cudaMalloc allowed)
__device__ float g_score[NB * 72];            // [b][0..63] token scores, [64] subject+ba
__device__ float g_pooled[NB * NH];
__device__ float g_part[HSPLIT * NB * NO];    // 4.7 MB partials (L2-resident)
__device__ unsigned long long g_bar[4];       // monotonic barrier counters
__device__ float g_sink;                      // prefetch DCE sink

// grid-wide barrier: monotonic epoch counter, reset-free across graph replays
__device__ __forceinline__ void grid_barrier(int i)
{
    __syncthreads();
    if (threadIdx.x == 0) {
        __threadfence();
        unsigned long long ticket = atomicAdd(&g_bar[i], 1ULL);
        unsigned long long target = (ticket / GRID + 1ULL) * GRID;
        volatile unsigned long long* p = &g_bar[i];
        while (*p < target) __nanosleep(32);
        __threadfence();
    }
    __syncthreads();
}

__global__ void __launch_bounds__(TPB)
fused_kernel(const float* __restrict__ hidden,        // (B,S,H)
             const int*   __restrict__ token_idxs,    // (B,K) sorted
             const float* __restrict__ subject_hidden,// (B,H)
             const float* __restrict__ Wa,            // (2H,1)
             const float* __restrict__ ba,            // (1,)
             const float* __restrict__ Wo,            // (H,O)
             const float* __restrict__ bo,            // (O,)
             float*       __restrict__ out_t,         // (B,O)
             float*       __restrict__ out_aw)        // (B,S)
{
    const int tid  = threadIdx.x;
    const int warp = tid >> 5;
    const int lane = tid & 31;
    const int blk  = blockIdx.x;

    __shared__ int   s_idx[NK];
    __shared__ float s_sc[NK];
    __shared__ float s_w[NK];
    __shared__ float s_hi[256];                 // pool upper-half partials
    __shared__ float s_p[NB * HCHUNK];          // GEMM pooled staging (2 KB)

    // ======== PHASE A: zero aw + 2080 score dots (1/warp) + Wo L2 prefetch ========
    {
        int gid = blk * TPB + tid;
        if (gid < (NB * NS) / 4)
            ((float4*)out_aw)[gid] = make_float4(0.f, 0.f, 0.f, 0.f);

        const int wgid = blk * NWARP + warp;    // 0..2367
        if (wgid < NTASKS) {
            const float4* row;
            const float4* wv;
            int b, j;
            if (wgid < NB * NK) {
                b = wgid >> 6; j = wgid & 63;
                int ix = token_idxs[b * NK + j];
                row = (const float4*)(hidden + ((size_t)b * NS + ix) * NH);
                wv  = (const float4*)(Wa + NH);
            } else {
                b = wgid - NB * NK; j = 64;
                row = (const float4*)(subject_hidden + (size_t)b * NH);
                wv  = (const float4*)Wa;
            }
            float p = 0.f;
            #pragma unroll
            for (int i = 0; i < 6; i++) {       // 6*32 float4 = 768 floats
                float4 r = row[i * 32 + lane];
                float4 w = wv[i * 32 + lane];
                p = fmaf(r.x, w.x, p); p = fmaf(r.y, w.y, p);
                p = fmaf(r.z, w.z, p); p = fmaf(r.w, w.w, p);
            }
            #pragma unroll
            for (int o = 16; o; o >>= 1) p += __shfl_xor_sync(0xffffffffu, p, o);
            if (lane == 0)
                g_score[b * 72 + j] = (j == 64) ? (p + ba[0]) : p;
        } else {
            // 288 surplus warps prefetch Wo (2.36 MB) into L2, overlapped
            const float4* w4 = (const float4*)Wo;
            const int pid = wgid - NTASKS;      // 0..287
            float acc = 0.f;
            #pragma unroll 4
            for (int i = pid * 32 + lane; i < (NH * NO) / 4; i += 288 * 32) {
                float4 w = w4[i];
                acc += w.x + w.y + w.z + w.w;
            }
            if (acc == 123456789.0f) g_sink = acc;   // never true; defeats DCE
        }
    }
    grid_barrier(0);

    // ======== PHASE C: softmax (per-block local) + pool (row-split x2) + scatter ========
    if (blk < NB * 3) {                          // (b, 256-col tile)
        const int b    = blk / 3;
        const int tile = blk % 3;

        if (tid < NK) {
            s_idx[tid] = token_idxs[b * NK + tid];
            s_sc[tid]  = g_score[b * 72 + tid];
        }
        __syncthreads();
        const float subj = g_score[b * 72 + 64];

        if (tid < 32) {                          // dedup'd softmax, 2 entries/lane
            float sc[2]; bool v[2];
            float m = -1e30f;
            #pragma unroll
            for (int r = 0; r < 2; r++) {
                int j = lane + 32 * r;
                v[r]  = (j == 0) || (s_idx[j] != s_idx[j - 1]);
                sc[r] = s_sc[j] + subj;
                m = fmaxf(m, v[r] ? sc[r] : -1e30f);
            }
            #pragma unroll
            for (int o = 16; o; o >>= 1) m = fmaxf(m, __shfl_xor_sync(0xffffffffu, m, o));
            float e[2], sum = 0.f;
            #pragma unroll
            for (int r = 0; r < 2; r++) { e[r] = v[r] ? expf(sc[r] - m) : 0.f; sum += e[r]; }
            #pragma unroll
            for (int o = 16; o; o >>= 1) sum += __shfl_xor_sync(0xffffffffu, sum, o);
            float inv = 1.0f / sum;
            #pragma unroll
            for (int r = 0; r < 2; r++) s_w[lane + 32 * r] = e[r] * inv;
        }
        __syncthreads();

        if (tile == 0 && tid < NK) {             // scatter aw (row zeroed in phase A)
            bool valid = (tid == 0) || (s_idx[tid] != s_idx[tid - 1]);
            if (valid) out_aw[(size_t)b * NS + s_idx[tid]] = s_w[tid];
        }

        // pool: 256 cols, 2 threads per col (rows 0-31 / 32-63), L2-hot rows
        const float* hb  = hidden + (size_t)b * NS * NH;
        const int    col = tile * 256 + (tid & 255);
        const int    j0  = (tid < 256) ? 0 : 32;
        float acc = 0.f;
        #pragma unroll
        for (int jj = 0; jj < 32; jj++) {
            int j = j0 + jj;
            acc = fmaf(s_w[j], hb[(size_t)s_idx[j] * NH + col], acc);
        }
        if (tid >= 256) s_hi[tid - 256] = acc;
        __syncthreads();
        if (tid < 256) g_pooled[b * NH + col] = acc + s_hi[tid];
    }
    grid_barrier(1);

    // ======== PHASE D: GEMM partials (Wo from L2, read once) ========
    if (blk < 3 * HSPLIT) {                      // 144 tasks: (o-tile of 256) x h-split
        const int otile = blk % 3;
        const int hs    = blk / 3;
        const int h0    = hs * HCHUNK;

        {   // stage pooled[32b x 16h] into smem: s_p[bb*HCHUNK+hh]
            int bb = tid >> 4, hh = tid & 15;    // tid < 512 covers all 512 entries
            s_p[tid] = g_pooled[bb * NH + h0 + hh];
        }
        __syncthreads();

        const int o  = otile * 256 + (tid & 255);
        const int bg = tid >> 8;                 // 0/1 -> batches [bg*16, bg*16+16)
        float acc[16];
        #pragma unroll
        for (int bb = 0; bb < 16; bb++) acc[bb] = 0.f;

        const float* w  = Wo + (size_t)h0 * NO + o;
        const float* sp = s_p + (bg * 16) * HCHUNK;
        #pragma unroll
        for (int hh = 0; hh < HCHUNK; hh++) {
            float wv = w[(size_t)hh * NO];
            #pragma unroll
            for (int bb = 0; bb < 16; bb++)
                acc[bb] = fmaf(sp[bb * HCHUNK + hh], wv, acc[bb]);
        }
        float* dst = g_part + ((size_t)hs * NB + bg * 16) * NO + o;
        #pragma unroll
        for (int bb = 0; bb < 16; bb++)
            dst[(size_t)bb * NO] = acc[bb];
    }
    grid_barrier(2);

    // ======== PHASE E: reduce partials + bias + tanh ========
    {
        int gid = blk * TPB + tid;
        if (gid < NB * NO) {
            float sum = bo[gid % NO];
            #pragma unroll
            for (int hs = 0; hs < HSPLIT; hs++)
                sum += g_part[(size_t)hs * NB * NO + gid];
            out_t[gid] = tanhf(sum);
        }
    }
}

// ---------------------------------------------------------------------------
extern "C" void kernel_launch(void* const* d_in, const int* in_sizes, int n_in,
                              void* d_out, int out_size)
{
    const float* hidden         = (const float*)d_in[0];
    const int*   token_idxs     = (const int*)  d_in[1];
    const float* subject_hidden = (const float*)d_in[2];
    const float* Wa             = (const float*)d_in[3];
    const float* ba             = (const float*)d_in[4];
    const float* Wo             = (const float*)d_in[5];
    const float* bo             = (const float*)d_in[6];

    float* out_transformed = (float*)d_out;              // (B,O)
    float* out_aw          = (float*)d_out + NB * NO;    // (B,S)

    fused_kernel<<<GRID, TPB>>>(hidden, token_idxs, subject_hidden,
                                Wa, ba, Wo, bo, out_transformed, out_aw);
}